// round 14
// baseline (speedup 1.0000x reference)
#include <cuda_runtime.h>
#include <cstdint>

// ============================================================================
// PillarFeatureNet (exact algebraic restructuring):
// pass1: raw/per-voxel moments (R4-proven: shfl butterflies, 64-reg cap,
//        4 blocks/SM, no prefetch); stores (px,py); last block finalizes BN
//        params + self-resets state.
// pass2: folded 4->64 linear; scalar FFMA (proven best issue%); head prefetch;
//        NaN tail padding (uniform ceil(k/2) loop); off folded into chain;
//        B/T coefficients as packed float2 in smem.
// ============================================================================

#define MAX_N 60000
#define BLOCK 256
#define GRID1 592              /* 148 SMs * 4 blocks (pass1, 64-reg cap) */
#define GRID2 740              /* 148 SMs * 5 blocks (pass2)             */
#define NWARP (BLOCK / 32)
#define NSTAT 54

// stats layout:
// [0..13]  G1_i (4), G2_ij (10: 00,01,02,03,11,12,13,22,23,33)
// [14..25] U_ij = sum m_i sv_j (i:0..2, j:0..3) at 14+4i+j
// [26..29] Qx_j = sum px sv_j      [30..33] Qy_j = sum py sv_j
// [34..39] V_ij = sum sa_i m_j (sym 3x3)   [40..42] Wx_i  [43..45] Wy_i
// [46..48] Ksa_i  [49..51] Rxx,Rxy,Ryy  [52..53] Lx,Ly
__device__ float    g_stats[NSTAT];       // zero at load; last block re-zeroes
__device__ unsigned g_count;              // zero at load; last block resets
__device__ float    g_params[10 * 64];    // rows: A0..A3, B0..B4, T
__device__ float4   g_meta[MAX_N];        // (m0, m1, m2, k)
__device__ float2   g_pxy[MAX_N];         // (px, py) valid where k>0

__constant__ unsigned char c_iA[32] = {3,3,3,4,4,5, 3,4,5, 3,4,5, 3,4,5, 8,8,9, 8,9,
                                       10,10,10,10,10,10,10,10,10,10,10,10};
__constant__ unsigned char c_iB[32] = {0,1,2,1,2,2, 6,6,6, 7,7,7, 10,10,10, 6,7,7, 10,10,
                                       10,10,10,10,10,10,10,10,10,10,10,10};

__device__ __forceinline__ float wsum(float x) {
#pragma unroll
    for (int o = 16; o; o >>= 1) x += __shfl_xor_sync(0xffffffffu, x, o);
    return x;
}

// ---------------------------------------------------------------------------
// Pass 1 + fused finalize (R4-proven: no prefetch, 64-reg cap -> 4 blocks/SM)
// ---------------------------------------------------------------------------
__global__ void __launch_bounds__(BLOCK, 4) k_pass1(
    const float4* __restrict__ vox, const int* __restrict__ npts,
    const int4* __restrict__ coors, const float* __restrict__ Wm,
    const float* __restrict__ gm, const float* __restrict__ bt,
    float invNP, int N)
{
    const int lane = threadIdx.x & 31;
    const int wid  = threadIdx.x >> 5;
    const int warp = blockIdx.x * NWARP + wid;
    const int nwarps = GRID1 * NWARP;

    __shared__ float q_sm[NWARP][12];
    __shared__ float red[NWARP][NSTAT];

    float a[14];
#pragma unroll
    for (int i = 0; i < 14; i++) a[i] = 0.0f;
    float UQ[20];
#pragma unroll
    for (int i = 0; i < 20; i++) UQ[i] = 0.0f;
    float pv = 0.0f;
    const int ia = c_iA[lane], ib = c_iB[lane];

    for (int n = warp; n < N; n += nwarps) {
        const int k = __ldg(&npts[n]);
        if (k == 0) {
            if (lane == 0) g_meta[n] = make_float4(0.0f, 0.0f, 0.0f, 0.0f);
            continue;
        }
        const float4 v = vox[(size_t)n * 32 + lane];
        float4 u = v;
        if (lane >= k) { u.x = 0.f; u.y = 0.f; u.z = 0.f; u.w = 0.f; }

        a[0]  += u.x;        a[1]  += u.y;        a[2]  += u.z;        a[3]  += u.w;
        a[4]  += u.x * u.x;  a[5]  += u.x * u.y;  a[6]  += u.x * u.z;  a[7]  += u.x * u.w;
        a[8]  += u.y * u.y;  a[9]  += u.y * u.z;  a[10] += u.y * u.w;
        a[11] += u.z * u.z;  a[12] += u.z * u.w;  a[13] += u.w * u.w;

        // unmasked all-point xyz sums (reference's points_mean numerator)
        const float sa0 = wsum(v.x), sa1 = wsum(v.y), sa2 = wsum(v.z);
        const float kf = (float)k, inv = 1.0f / kf;
        const float m0 = sa0 * inv, m1 = sa1 * inv, m2 = sa2 * inv;
        const int4 cc = coors[n];
        const float px = (float)cc.y * 0.1f + (0.05f - 20.0f);
        const float py = (float)cc.z * 0.1f + (0.05f - 20.0f);

        UQ[0]  += m0 * u.x;  UQ[1]  += m0 * u.y;  UQ[2]  += m0 * u.z;  UQ[3]  += m0 * u.w;
        UQ[4]  += m1 * u.x;  UQ[5]  += m1 * u.y;  UQ[6]  += m1 * u.z;  UQ[7]  += m1 * u.w;
        UQ[8]  += m2 * u.x;  UQ[9]  += m2 * u.y;  UQ[10] += m2 * u.z;  UQ[11] += m2 * u.w;
        UQ[12] += px * u.x;  UQ[13] += px * u.y;  UQ[14] += px * u.z;  UQ[15] += px * u.w;
        UQ[16] += py * u.x;  UQ[17] += py * u.y;  UQ[18] += py * u.z;  UQ[19] += py * u.w;

        if (lane == 0) {
            float4* qs = (float4*)q_sm[wid];
            qs[0] = make_float4(m0, m1, m2, sa0);
            qs[1] = make_float4(sa1, sa2, px, py);
            qs[2] = make_float4(kf * px, kf * py, 1.0f, 0.0f);
            g_meta[n] = make_float4(m0, m1, m2, kf);
            g_pxy[n]  = make_float2(px, py);
        }
        __syncwarp();
        pv = fmaf(q_sm[wid][ia], q_sm[wid][ib], pv);
        __syncwarp();
    }

#pragma unroll
    for (int i = 0; i < 14; i++) a[i] = wsum(a[i]);
#pragma unroll
    for (int i = 0; i < 20; i++) UQ[i] = wsum(UQ[i]);
    if (lane == 0) {
#pragma unroll
        for (int i = 0; i < 14; i++) red[wid][i] = a[i];
#pragma unroll
        for (int i = 0; i < 20; i++) red[wid][14 + i] = UQ[i];
    }
    if (lane < 20) red[wid][34 + lane] = pv;
    __syncthreads();
    if (threadIdx.x < NSTAT) {
        float s = 0.0f;
#pragma unroll
        for (int w = 0; w < NWARP; w++) s += red[w][threadIdx.x];
        atomicAdd(&g_stats[threadIdx.x], s);
    }
    __threadfence();
    __shared__ unsigned s_last;
    if (threadIdx.x == 0) s_last = atomicAdd(&g_count, 1u);
    __syncthreads();
    if (s_last != GRID1 - 1) return;
    __threadfence();

    // ---------------- finalize (last block only) ----------------
    __shared__ float S[9];
    __shared__ float M[9][9];
    if (threadIdx.x == 0) {
        float st[NSTAT];
#pragma unroll
        for (int i = 0; i < NSTAT; i++) st[i] = __ldcg(&g_stats[i]);

        auto G2 = [&](int i, int j) -> float {
            if (i > j) { int t = i; i = j; j = t; }
            const int base[4] = {0, 4, 7, 9};
            return st[4 + base[i] + (j - i)];
        };
        auto U = [&](int i, int j) -> float { return st[14 + i * 4 + j]; };
        auto V = [&](int i, int j) -> float {
            int lo = i < j ? i : j, hi = i < j ? j : i;
            const int b3[3] = {0, 3, 5};
            return st[34 + b3[lo] + (hi - lo)];
        };
        const float* Qx = st + 26; const float* Qy = st + 30;
        const float* Wx = st + 40; const float* Wy = st + 43; const float* Ksa = st + 46;
        const float Rxx = st[49], Rxy = st[50], Ryy = st[51], Lx = st[52], Ly = st[53];

        S[0] = st[0]; S[1] = st[1]; S[2] = st[2]; S[3] = st[3];
        S[4] = st[0] - Ksa[0]; S[5] = st[1] - Ksa[1]; S[6] = st[2] - Ksa[2];
        S[7] = st[0] - Lx;     S[8] = st[1] - Ly;

        for (int i = 0; i < 4; i++)
            for (int j = 0; j < 4; j++) M[i][j] = G2(i, j);
        for (int j = 0; j < 3; j++)
            for (int i = 0; i < 4; i++) {
                const float m = G2(i, j) - U(j, i);
                M[i][4 + j] = m; M[4 + j][i] = m;
            }
        for (int i = 0; i < 3; i++)
            for (int j = 0; j < 3; j++)
                M[4 + i][4 + j] = G2(i, j) - U(i, j) - U(j, i) + V(i, j);
        for (int i = 0; i < 4; i++) {
            float m = G2(i, 0) - Qx[i]; M[i][7] = m; M[7][i] = m;
            m       = G2(i, 1) - Qy[i]; M[i][8] = m; M[8][i] = m;
        }
        for (int i = 0; i < 3; i++) {
            float m = G2(i, 0) - Qx[i] - U(i, 0) + Wx[i]; M[4 + i][7] = m; M[7][4 + i] = m;
            m       = G2(i, 1) - Qy[i] - U(i, 1) + Wy[i]; M[4 + i][8] = m; M[8][4 + i] = m;
        }
        M[7][7] = G2(0, 0) - 2.0f * Qx[0] + Rxx;
        M[7][8] = G2(0, 1) - Qx[1] - Qy[0] + Rxy; M[8][7] = M[7][8];
        M[8][8] = G2(1, 1) - 2.0f * Qy[1] + Ryy;
    }
    __syncthreads();

    if (threadIdx.x < NSTAT) g_stats[threadIdx.x] = 0.0f;
    if (threadIdx.x == 0)    g_count = 0u;

    const int o = threadIdx.x;
    if (o < 64) {
        float w[9];
#pragma unroll
        for (int j = 0; j < 9; j++) w[j] = Wm[o * 9 + j];
        float mean = 0.0f;
#pragma unroll
        for (int j = 0; j < 9; j++) mean += w[j] * S[j];
        mean *= invNP;
        float e2 = 0.0f;
#pragma unroll
        for (int i = 0; i < 9; i++) {
            float acc = 0.0f;
#pragma unroll
            for (int j = 0; j < 9; j++) acc += w[j] * M[i][j];
            e2 += w[i] * acc;
        }
        e2 *= invNP;
        const float var = e2 - mean * mean;
        const float sc  = gm[o] * rsqrtf(var + 1e-3f);
        const float sh  = bt[o] - mean * sc;

        g_params[0 * 64 + o] = sc * (w[0] + w[4] + w[7]);
        g_params[1 * 64 + o] = sc * (w[1] + w[5] + w[8]);
        g_params[2 * 64 + o] = sc * (w[2] + w[6]);
        g_params[3 * 64 + o] = sc * w[3];
        g_params[4 * 64 + o] = sc * w[4];
        g_params[5 * 64 + o] = sc * w[5];
        g_params[6 * 64 + o] = sc * w[6];
        g_params[7 * 64 + o] = sc * w[7];
        g_params[8 * 64 + o] = sc * w[8];
        g_params[9 * 64 + o] = sh;
    }
}

// ---------------------------------------------------------------------------
// Pass 2: warp/voxel; lane = channels (2l, 2l+1). Scalar FFMA; A-coeffs in
// regs, B/T as packed float2 in smem; head prefetch (meta,pxy,vox); NaN tail
// padding -> uniform ceil(k/2) loop; off folded into chain base.
// ---------------------------------------------------------------------------
__global__ void __launch_bounds__(BLOCK, 5) k_pass2(
    const float4* __restrict__ vox, float2* __restrict__ out, int N)
{
    const int lane = threadIdx.x & 31;
    const int wid  = threadIdx.x >> 5;
    const int warp = blockIdx.x * NWARP + wid;
    const int nwarps = GRID2 * NWARP;

    // B0..B4, T rows staged in smem as per-channel-pair float2
    __shared__ float2 sB2[6][32];
    if (threadIdx.x < 192) {
        const int r = threadIdx.x >> 5, l = threadIdx.x & 31;
        sB2[r][l] = make_float2(g_params[(4 + r) * 64 + 2 * l],
                                g_params[(4 + r) * 64 + 2 * l + 1]);
    }

    // A rows: 8 scalar regs (channel pair per row)
    const float2* P = (const float2*)g_params;   // row r, pair: P[r*32 + lane]
    const float2 A0 = P[0 * 32 + lane];
    const float2 A1 = P[1 * 32 + lane];
    const float2 A2 = P[2 * 32 + lane];
    const float2 A3 = P[3 * 32 + lane];
    __syncthreads();

    __shared__ __align__(16) float4 pts[NWARP][32];
    const float NEG_INF = __int_as_float(0xff800000);
    const float QNAN    = __int_as_float(0x7fffffff);

    // prefetch head state for voxel n
    float4 pre_meta = make_float4(0.f, 0.f, 0.f, 0.f);
    float2 pre_pxy  = make_float2(0.f, 0.f);
    float4 pre_v    = make_float4(0.f, 0.f, 0.f, 0.f);
    int n = warp;
    if (n < N) {
        pre_meta = g_meta[n];
        pre_pxy  = g_pxy[n];
        pre_v    = vox[(size_t)n * 32 + lane];
    }

    for (; n < N; n += nwarps) {
        const float4 meta = pre_meta;
        const float2 pxy  = pre_pxy;
        const float4 v    = pre_v;
        const int n2 = n + nwarps;
        if (n2 < N) {
            pre_meta = g_meta[n2];
            pre_pxy  = g_pxy[n2];
            pre_v    = vox[(size_t)n2 * 32 + lane];
        }

        const int k = (int)meta.w;
        if (k == 0) {
            out[(size_t)n * 32 + lane] = make_float2(0.0f, 0.0f);
            continue;
        }
        // NaN padding for invalid lanes: fmaxf drops NaN operands
        float4 u = v;
        if (lane >= k) { u.x = QNAN; u.y = QNAN; u.z = QNAN; u.w = QNAN; }
        pts[wid][lane] = u;

        const float2 B0 = sB2[0][lane], B1 = sB2[1][lane], B2 = sB2[2][lane];
        const float2 B3 = sB2[3][lane], B4 = sB2[4][lane], T  = sB2[5][lane];
        float ta = B0.x * meta.x;
        ta = fmaf(B1.x, meta.y, ta); ta = fmaf(B2.x, meta.z, ta);
        ta = fmaf(B3.x, pxy.x, ta);  ta = fmaf(B4.x, pxy.y, ta);
        const float offa = T.x - ta;
        float tb = B0.y * meta.x;
        tb = fmaf(B1.y, meta.y, tb); tb = fmaf(B2.y, meta.z, tb);
        tb = fmaf(B3.y, pxy.x, tb);  tb = fmaf(B4.y, pxy.y, tb);
        const float offb = T.y - tb;

        __syncwarp();
        float ra0 = NEG_INF, ra1 = NEG_INF, rb0 = NEG_INF, rb1 = NEG_INF;
        const int k2 = (k + 1) >> 1;       // NaN padding makes this uniform
#pragma unroll 2
        for (int j = 0; j < k2; j++) {
            const float4 u0 = pts[wid][2 * j];
            const float4 u1 = pts[wid][2 * j + 1];
            const float y0a = fmaf(u0.x, A0.x, fmaf(u0.y, A1.x, fmaf(u0.z, A2.x, fmaf(u0.w, A3.x, offa))));
            const float y0b = fmaf(u0.x, A0.y, fmaf(u0.y, A1.y, fmaf(u0.z, A2.y, fmaf(u0.w, A3.y, offb))));
            const float y1a = fmaf(u1.x, A0.x, fmaf(u1.y, A1.x, fmaf(u1.z, A2.x, fmaf(u1.w, A3.x, offa))));
            const float y1b = fmaf(u1.x, A0.y, fmaf(u1.y, A1.y, fmaf(u1.z, A2.y, fmaf(u1.w, A3.y, offb))));
            ra0 = fmaxf(ra0, y0a); rb0 = fmaxf(rb0, y0b);
            ra1 = fmaxf(ra1, y1a); rb1 = fmaxf(rb1, y1b);
        }
        const float ra = fmaxf(fmaxf(ra0, ra1), 0.0f);
        const float rb = fmaxf(fmaxf(rb0, rb1), 0.0f);
        out[(size_t)n * 32 + lane] = make_float2(ra, rb);
        __syncwarp();
    }
}

// ---------------------------------------------------------------------------
extern "C" void kernel_launch(void* const* d_in, const int* in_sizes, int n_in,
                              void* d_out, int out_size)
{
    const float* voxels = (const float*)d_in[0];
    const int*   npts   = (const int*)d_in[1];
    const int*   coors  = (const int*)d_in[2];
    const float* W      = (const float*)d_in[3];
    const float* gamma  = (const float*)d_in[4];
    const float* beta   = (const float*)d_in[5];
    float*       out    = (float*)d_out;
    const int N = in_sizes[1];

    k_pass1<<<GRID1, BLOCK>>>((const float4*)voxels, npts, (const int4*)coors,
                              W, gamma, beta, 1.0f / ((float)N * 32.0f), N);
    k_pass2<<<GRID2, BLOCK>>>((const float4*)voxels, (float2*)out, N);
}

// round 15
// speedup vs baseline: 1.1087x; 1.1087x over previous
#include <cuda_runtime.h>
#include <cstdint>

// ============================================================================
// PillarFeatureNet — FUSED single-pass + streaming epilogue.
//
// Identity: sign(sc_c) = sign(gamma_c) is known pre-statistics, so
//   max_p(BN-relu input) = |sc|·max_p( s_c·x_raw ) + sh,  s_c = sign(gamma_c).
// k_fused: per voxel computes global moments AND per-channel extreme of the
//   raw folded 4->64 linear (sign-folded coefficients). Last block finalizes
//   (|sc|, sh) per channel and self-resets state for graph replay.
// k_post: out = k>0 ? relu(|sc|·ext + sh) : 0   (pure streaming).
// ============================================================================

#define MAX_N 60000
#define BLOCK 256
#define GRID1 592              /* 148 SMs * 4 blocks (fused, 64-reg cap) */
#define GRID2 888
#define NWARP (BLOCK / 32)
#define NSTAT 54

// stats layout (identical to proven finalize):
// [0..3] G1  [4..13] G2  [14..25] U(m_i sv_j)  [26..29] Qx  [30..33] Qy
// [34..39] V(sa_i m_j sym)  [40..42] Wx  [43..45] Wy  [46..48] Ksa
// [49..51] R  [52..53] L
__device__ float    g_stats[NSTAT];
__device__ unsigned g_count;
__device__ float2   g_scsh[64];          // (|sc|, sh) per channel
__device__ float2   g_ext[MAX_N * 32];   // per-voxel per-lane channel-pair extremes

// distributed per-voxel scalar terms. q vector (smem, 16):
// [0..2]=m  [3..5]=sa  [6]=px [7]=py [8]=kpx [9]=kpy [10]=1 [11..14]=sv [15]=0
// term t -> stats index (t<4 ? t : t+10). lane l: pv0=term l, pv1=term 32+l (l<12).
__constant__ unsigned char cA[64] = {
    11,12,13,14,  0,0,0,0, 1,1,1,1, 2,2,2,2,  6,6,6,6,  7,7,7,7,
    3,3,3,4,4,5,  3,4,
    5, 3,4,5, 3,4,5, 8,8,9, 8,9,
    15,15,15,15,15,15,15,15,15,15,15,15,15,15,15,15,15,15,15,15};
__constant__ unsigned char cB[64] = {
    10,10,10,10,  11,12,13,14, 11,12,13,14, 11,12,13,14,  11,12,13,14,  11,12,13,14,
    0,1,2,1,2,2,  6,6,
    6, 7,7,7, 10,10,10, 6,7,7, 10,10,
    15,15,15,15,15,15,15,15,15,15,15,15,15,15,15,15,15,15,15,15};

__device__ __forceinline__ float wsum(float x) {
#pragma unroll
    for (int o = 16; o; o >>= 1) x += __shfl_xor_sync(0xffffffffu, x, o);
    return x;
}

// ---------------------------------------------------------------------------
// Fused kernel
// ---------------------------------------------------------------------------
__global__ void __launch_bounds__(BLOCK, 4) k_fused(
    const float4* __restrict__ vox, const int* __restrict__ npts,
    const int4* __restrict__ coors, const float* __restrict__ Wm,
    const float* __restrict__ gm, const float* __restrict__ bt,
    float invNP, int N)
{
    const int lane = threadIdx.x & 31;
    const int wid  = threadIdx.x >> 5;
    const int warp = blockIdx.x * NWARP + wid;
    const int nwarps = GRID1 * NWARP;

    __shared__ float  q_sm[NWARP][16];
    __shared__ float  red[NWARP][NSTAT];
    __shared__ __align__(8) float2 sA2[4][32];   // sign-folded A' (channel pairs)
    __shared__ __align__(8) float2 sB2[5][32];   // sign-folded B'
    __shared__ __align__(16) float4 pts[NWARP][32];

    // Build sign-folded raw coefficient tables (per block, from inputs only)
    if (threadIdx.x < 64) {
        const int o = threadIdx.x;
        float w[9];
#pragma unroll
        for (int j = 0; j < 9; j++) w[j] = Wm[o * 9 + j];
        const float s = (gm[o] < 0.0f) ? -1.0f : 1.0f;
        ((float*)sA2[0])[o] = s * (w[0] + w[4] + w[7]);
        ((float*)sA2[1])[o] = s * (w[1] + w[5] + w[8]);
        ((float*)sA2[2])[o] = s * (w[2] + w[6]);
        ((float*)sA2[3])[o] = s * w[3];
        ((float*)sB2[0])[o] = s * w[4];
        ((float*)sB2[1])[o] = s * w[5];
        ((float*)sB2[2])[o] = s * w[6];
        ((float*)sB2[3])[o] = s * w[7];
        ((float*)sB2[4])[o] = s * w[8];
    }
    __syncthreads();

    const float2 A0 = sA2[0][lane], A1 = sA2[1][lane];
    const float2 A2 = sA2[2][lane], A3 = sA2[3][lane];

    float a[10];                      // G2 only (G1 distributed)
#pragma unroll
    for (int i = 0; i < 10; i++) a[i] = 0.0f;
    float pv0 = 0.0f, pv1 = 0.0f;
    const int iA0 = cA[lane],      iB0 = cB[lane];
    const int iA1 = cA[32 + lane], iB1 = cB[32 + lane];

    const float NEG_INF = __int_as_float(0xff800000);
    const float QNAN    = __int_as_float(0x7fffffff);

    for (int n = warp; n < N; n += nwarps) {
        const int k = __ldg(&npts[n]);
        const float4 v = vox[(size_t)n * 32 + lane];   // hoisted: MLP with npts
        const int4  cc = coors[n];
        if (k == 0) continue;                          // post-kernel zeroes these

        float4 uz = v;                                 // zero-masked (moments)
        if (lane >= k) { uz.x = 0.f; uz.y = 0.f; uz.z = 0.f; uz.w = 0.f; }

        a[0] += uz.x * uz.x;  a[1] += uz.x * uz.y;  a[2] += uz.x * uz.z;  a[3] += uz.x * uz.w;
        a[4] += uz.y * uz.y;  a[5] += uz.y * uz.z;  a[6] += uz.y * uz.w;
        a[7] += uz.z * uz.z;  a[8] += uz.z * uz.w;  a[9] += uz.w * uz.w;

        // butterflies: unmasked sa (cluster-mean numerator) + masked sv
        const float sa0 = wsum(v.x),  sa1 = wsum(v.y),  sa2 = wsum(v.z);
        const float sv0 = wsum(uz.x), sv1 = wsum(uz.y), sv2 = wsum(uz.z), sv3 = wsum(uz.w);
        const float kf = (float)k, inv = 1.0f / kf;
        const float m0 = sa0 * inv, m1 = sa1 * inv, m2 = sa2 * inv;
        const float px = (float)cc.y * 0.1f + (0.05f - 20.0f);
        const float py = (float)cc.z * 0.1f + (0.05f - 20.0f);

        if (lane == 0) {
            float4* qs = (float4*)q_sm[wid];
            qs[0] = make_float4(m0, m1, m2, sa0);
            qs[1] = make_float4(sa1, sa2, px, py);
            qs[2] = make_float4(kf * px, kf * py, 1.0f, sv0);
            qs[3] = make_float4(sv1, sv2, sv3, 0.0f);
        }
        float4 un = v;                                 // NaN-masked (extremes)
        if (lane >= k) { un.x = QNAN; un.y = QNAN; un.z = QNAN; un.w = QNAN; }
        pts[wid][lane] = un;
        __syncwarp();
        pv0 = fmaf(q_sm[wid][iA0], q_sm[wid][iB0], pv0);
        pv1 = fmaf(q_sm[wid][iA1], q_sm[wid][iB1], pv1);

        const float2 B0 = sB2[0][lane], B1 = sB2[1][lane], B2 = sB2[2][lane];
        const float2 B3 = sB2[3][lane], B4 = sB2[4][lane];
        float ta = B0.x * m0;
        ta = fmaf(B1.x, m1, ta); ta = fmaf(B2.x, m2, ta);
        ta = fmaf(B3.x, px, ta); ta = fmaf(B4.x, py, ta);
        const float offa = -ta;
        float tb = B0.y * m0;
        tb = fmaf(B1.y, m1, tb); tb = fmaf(B2.y, m2, tb);
        tb = fmaf(B3.y, px, tb); tb = fmaf(B4.y, py, tb);
        const float offb = -tb;

        float ra = NEG_INF, rb = NEG_INF;
        const int k2 = (k + 1) >> 1;
#pragma unroll 2
        for (int j = 0; j < k2; j++) {
            const float4 u0 = pts[wid][2 * j];
            const float4 u1 = pts[wid][2 * j + 1];
            const float y0a = fmaf(u0.x, A0.x, fmaf(u0.y, A1.x, fmaf(u0.z, A2.x, fmaf(u0.w, A3.x, offa))));
            const float y0b = fmaf(u0.x, A0.y, fmaf(u0.y, A1.y, fmaf(u0.z, A2.y, fmaf(u0.w, A3.y, offb))));
            const float y1a = fmaf(u1.x, A0.x, fmaf(u1.y, A1.x, fmaf(u1.z, A2.x, fmaf(u1.w, A3.x, offa))));
            const float y1b = fmaf(u1.x, A0.y, fmaf(u1.y, A1.y, fmaf(u1.z, A2.y, fmaf(u1.w, A3.y, offb))));
            ra = fmaxf(fmaxf(ra, y0a), y1a);
            rb = fmaxf(fmaxf(rb, y0b), y1b);
        }
        g_ext[(size_t)n * 32 + lane] = make_float2(ra, rb);
        __syncwarp();
    }

    // ---- reductions ----
#pragma unroll
    for (int i = 0; i < 10; i++) a[i] = wsum(a[i]);
    {
        const int d0 = (lane < 4) ? lane : lane + 10;
        red[wid][d0] = pv0;                      // stats 0..3, 14..41
        if (lane < 12) red[wid][42 + lane] = pv1; // stats 42..53
        if (lane == 0) {
#pragma unroll
            for (int i = 0; i < 10; i++) red[wid][4 + i] = a[i];  // G2
        }
    }
    __syncthreads();
    if (threadIdx.x < NSTAT) {
        float s = 0.0f;
#pragma unroll
        for (int w = 0; w < NWARP; w++) s += red[w][threadIdx.x];
        atomicAdd(&g_stats[threadIdx.x], s);
    }
    __threadfence();
    __shared__ unsigned s_last;
    if (threadIdx.x == 0) s_last = atomicAdd(&g_count, 1u);
    __syncthreads();
    if (s_last != GRID1 - 1) return;
    __threadfence();

    // ---------------- finalize (last block only) ----------------
    __shared__ float S[9];
    __shared__ float M[9][9];
    if (threadIdx.x == 0) {
        float st[NSTAT];
#pragma unroll
        for (int i = 0; i < NSTAT; i++) st[i] = __ldcg(&g_stats[i]);

        auto G2f = [&](int i, int j) -> float {
            if (i > j) { int t = i; i = j; j = t; }
            const int base[4] = {0, 4, 7, 9};
            return st[4 + base[i] + (j - i)];
        };
        auto U = [&](int i, int j) -> float { return st[14 + i * 4 + j]; };
        auto V = [&](int i, int j) -> float {
            int lo = i < j ? i : j, hi = i < j ? j : i;
            const int b3[3] = {0, 3, 5};
            return st[34 + b3[lo] + (hi - lo)];
        };
        const float* Qx = st + 26; const float* Qy = st + 30;
        const float* Wx = st + 40; const float* Wy = st + 43; const float* Ksa = st + 46;
        const float Rxx = st[49], Rxy = st[50], Ryy = st[51], Lx = st[52], Ly = st[53];

        S[0] = st[0]; S[1] = st[1]; S[2] = st[2]; S[3] = st[3];
        S[4] = st[0] - Ksa[0]; S[5] = st[1] - Ksa[1]; S[6] = st[2] - Ksa[2];
        S[7] = st[0] - Lx;     S[8] = st[1] - Ly;

        for (int i = 0; i < 4; i++)
            for (int j = 0; j < 4; j++) M[i][j] = G2f(i, j);
        for (int j = 0; j < 3; j++)
            for (int i = 0; i < 4; i++) {
                const float m = G2f(i, j) - U(j, i);
                M[i][4 + j] = m; M[4 + j][i] = m;
            }
        for (int i = 0; i < 3; i++)
            for (int j = 0; j < 3; j++)
                M[4 + i][4 + j] = G2f(i, j) - U(i, j) - U(j, i) + V(i, j);
        for (int i = 0; i < 4; i++) {
            float m = G2f(i, 0) - Qx[i]; M[i][7] = m; M[7][i] = m;
            m       = G2f(i, 1) - Qy[i]; M[i][8] = m; M[8][i] = m;
        }
        for (int i = 0; i < 3; i++) {
            float m = G2f(i, 0) - Qx[i] - U(i, 0) + Wx[i]; M[4 + i][7] = m; M[7][4 + i] = m;
            m       = G2f(i, 1) - Qy[i] - U(i, 1) + Wy[i]; M[4 + i][8] = m; M[8][4 + i] = m;
        }
        M[7][7] = G2f(0, 0) - 2.0f * Qx[0] + Rxx;
        M[7][8] = G2f(0, 1) - Qx[1] - Qy[0] + Rxy; M[8][7] = M[7][8];
        M[8][8] = G2f(1, 1) - 2.0f * Qy[1] + Ryy;
    }
    __syncthreads();

    if (threadIdx.x < NSTAT) g_stats[threadIdx.x] = 0.0f;
    if (threadIdx.x == 0)    g_count = 0u;

    const int o = threadIdx.x;
    if (o < 64) {
        float w[9];
#pragma unroll
        for (int j = 0; j < 9; j++) w[j] = Wm[o * 9 + j];
        float mean = 0.0f;
#pragma unroll
        for (int j = 0; j < 9; j++) mean += w[j] * S[j];
        mean *= invNP;
        float e2 = 0.0f;
#pragma unroll
        for (int i = 0; i < 9; i++) {
            float acc = 0.0f;
#pragma unroll
            for (int j = 0; j < 9; j++) acc += w[j] * M[i][j];
            e2 += w[i] * acc;
        }
        e2 *= invNP;
        const float var = e2 - mean * mean;
        const float sc  = gm[o] * rsqrtf(var + 1e-3f);
        const float sh  = bt[o] - mean * sc;
        g_scsh[o] = make_float2(fabsf(sc), sh);
    }
}

// ---------------------------------------------------------------------------
// Post: out = k>0 ? relu(|sc|·ext + sh) : 0      (streaming, prefetched)
// ---------------------------------------------------------------------------
__global__ void __launch_bounds__(BLOCK) k_post(
    const int* __restrict__ npts, float2* __restrict__ out, int N)
{
    const int lane = threadIdx.x & 31;
    const int warp = (blockIdx.x * BLOCK + threadIdx.x) >> 5;
    const int nwarps = (GRID2 * BLOCK) >> 5;

    const float2 p0 = g_scsh[2 * lane];
    const float2 p1 = g_scsh[2 * lane + 1];

    int n = warp;
    int    pre_k = 0;
    float2 pre_e = make_float2(0.f, 0.f);
    if (n < N) { pre_k = __ldg(&npts[n]); pre_e = g_ext[(size_t)n * 32 + lane]; }

    for (; n < N; n += nwarps) {
        const int k = pre_k;
        const float2 e = pre_e;
        const int n2 = n + nwarps;
        if (n2 < N) { pre_k = __ldg(&npts[n2]); pre_e = g_ext[(size_t)n2 * 32 + lane]; }

        float2 o;
        if (k > 0) {
            o.x = fmaxf(fmaf(p0.x, e.x, p0.y), 0.0f);
            o.y = fmaxf(fmaf(p1.x, e.y, p1.y), 0.0f);
        } else {
            o.x = 0.0f; o.y = 0.0f;
        }
        out[(size_t)n * 32 + lane] = o;
    }
}

// ---------------------------------------------------------------------------
extern "C" void kernel_launch(void* const* d_in, const int* in_sizes, int n_in,
                              void* d_out, int out_size)
{
    const float* voxels = (const float*)d_in[0];
    const int*   npts   = (const int*)d_in[1];
    const int*   coors  = (const int*)d_in[2];
    const float* W      = (const float*)d_in[3];
    const float* gamma  = (const float*)d_in[4];
    const float* beta   = (const float*)d_in[5];
    float*       out    = (float*)d_out;
    const int N = in_sizes[1];

    k_fused<<<GRID1, BLOCK>>>((const float4*)voxels, npts, (const int4*)coors,
                              W, gamma, beta, 1.0f / ((float)N * 32.0f), N);
    k_post<<<GRID2, BLOCK>>>(npts, (float2*)out, N);
}